// round 16
// baseline (speedup 1.0000x reference)
#include <cuda_runtime.h>
#include <cstdint>

// GriddingDistance: trilinear scatter of two point clouds into voxel grids.
// SCALE=128, L=131, V=L^3, B=16, N=32768.
// Output: [pred_grid (16*V) | gt_grid (16*V)] floats.
//
// 2 launches (slab uses programmatic dependent launch to overlap its smem
// zero-fill prologue with the bin kernel's tail):
//  1) bin_kernel : one pass over all points, float4-vectorized reads.
//     Per-CTA partial mins + binning into per-CTA private segments keyed by
//     (x-slab, y-group). Payload packed to 8 bytes.
//  2) slab_kernel: one CTA per (cloud,batch,x-plane,y-group), scheduled
//     CENTER-OUT so heavy tiles run in early waves and the tail is the
//     near-empty edge slabs. Accumulates fixed-point in smem (packed 64-bit
//     atomics when aligned), stores 3 contiguous segments.

#define SCALE_F   64.0f
#define GRID_L    131
#define GRID_P    (GRID_L * GRID_L)
#define GRID_V    (GRID_L * GRID_L * GRID_L)
#define BATCH     16
#define NPTS      32768
#define NCB       32                  // 2 clouds * 16 batches
#define NSUB      8                   // bin CTAs per (cloud,batch)
#define NBINBLK   (NCB * NSUB)        // 256
#define PTS_BLK   (NPTS / NSUB)       // 4096
#define NKEY      256                 // 128 x-slabs * 2 y-groups
#define SCAP      48                  // slots per (CTA,key); mean ~16
#define SEGSTRIDE (NKEY * SCAP)       // uint2 elements per sub-segment
#define PLANE_PAD 8516                // 65*131=8515 rounded up to /4
#define BIN_T     512

#define FXS       33554432.0f        // 2^25 fixed-point scale
#define FXI       (1.0f / 33554432.0f)
#define Q16       65536.0f
#define Q16I      (1.0f / 65536.0f)

__device__ int   g_part[NBINBLK * 3];                  // per-CTA partial mins
__device__ int   g_cnt[NBINBLK * NKEY];                // per-CTA per-key counts
__device__ uint2 g_pay[(size_t)NBINBLK * SEGSTRIDE];   // packed payload

// payload: p.x = axq | (ayq<<16); p.y = azq | (pk<<16)
//          pk  = (fy+64) | ((fz+64)<<7)   (7 bits each)

// ---- launch 1: partial mins + private binning (float4 reads) ---------------
__global__ void __launch_bounds__(BIN_T) bin_kernel(const float* __restrict__ pred,
                                                    const float* __restrict__ gt) {
    __shared__ int scnt[NKEY];
    __shared__ int r0s[16], r1s[16], r2s[16];

    int tid = threadIdx.x;
    int blk = blockIdx.x;
    int cb  = blk / NSUB;
    int sub = blk % NSUB;
    int c   = cb >> 4;
    int b   = cb & 15;
    const float* cloud = (c ? gt : pred) + 3 * ((size_t)b * NPTS + sub * PTS_BLK);
    const float4* c4 = reinterpret_cast<const float4*>(cloud);  // 16B-aligned

    for (int i = tid; i < NKEY; i += BIN_T) scnt[i] = 0;
    __syncthreads();

    uint2* seg = g_pay + (size_t)blk * SEGSTRIDE;

    int mn0 = 0x7fffffff, mn1 = 0x7fffffff, mn2 = 0x7fffffff;

    const int nq = PTS_BLK / 4;                    // 1024 quads of 4 points
    for (int qi = tid; qi < nq; qi += BIN_T) {
        float4 A = c4[3 * qi + 0];
        float4 B = c4[3 * qi + 1];
        float4 C = c4[3 * qi + 2];
        float px[4], py[4], pz[4];
        px[0] = A.x; py[0] = A.y; pz[0] = A.z;
        px[1] = A.w; py[1] = B.x; pz[1] = B.y;
        px[2] = B.z; py[2] = B.w; pz[2] = C.x;
        px[3] = C.y; py[3] = C.z; pz[3] = C.w;

        #pragma unroll
        for (int k = 0; k < 4; k++) {
            float x = px[k] * SCALE_F;
            float y = py[k] * SCALE_F;
            float z = pz[k] * SCALE_F;
            float fx = floorf(x), fy = floorf(y), fz = floorf(z);
            // mins include padding points (reference: mins before masking)
            mn0 = min(mn0, (int)fx);
            mn1 = min(mn1, (int)fy);
            mn2 = min(mn2, (int)fz);
            if (x + y + z == 0.0f) continue;       // padding point: not binned
            int xkey = (int)fx + 64;               // 0..127
            if ((unsigned)xkey >= 128u) continue;  // safety (cannot happen)
            int f = (int)fy;                       // absolute fy, in [-64,63]

            unsigned axq = min(__float2uint_rn((x - fx) * Q16), 65535u);
            unsigned ayq = min(__float2uint_rn((y - fy) * Q16), 65535u);
            unsigned azq = min(__float2uint_rn((z - fz) * Q16), 65535u);
            unsigned pk  = (unsigned)(f + 64) | ((unsigned)((int)fz + 64) << 7);
            uint2 pay = make_uint2(axq | (ayq << 16), azq | (pk << 16));

            if (f <= 0) {                          // group0 (abs rows -64..0)
                int key = xkey * 2;
                int pos = atomicAdd(&scnt[key], 1);
                if (pos < SCAP) seg[key * SCAP + pos] = pay;
            }
            if (f >= 0) {                          // group1 (abs rows 1..64)
                int key = xkey * 2 + 1;
                int pos = atomicAdd(&scnt[key], 1);
                if (pos < SCAP) seg[key * SCAP + pos] = pay;
            }
        }
    }

    // reduce partial mins
    #pragma unroll
    for (int off = 16; off > 0; off >>= 1) {
        mn0 = min(mn0, __shfl_xor_sync(0xffffffffu, mn0, off));
        mn1 = min(mn1, __shfl_xor_sync(0xffffffffu, mn1, off));
        mn2 = min(mn2, __shfl_xor_sync(0xffffffffu, mn2, off));
    }
    int w = tid >> 5, l = tid & 31;
    if (l == 0) { r0s[w] = mn0; r1s[w] = mn1; r2s[w] = mn2; }
    __syncthreads();
    if (tid == 0) {
        int a = r0s[0], bb = r1s[0], cc = r2s[0];
        #pragma unroll
        for (int i = 1; i < 16; i++) {
            a = min(a, r0s[i]); bb = min(bb, r1s[i]); cc = min(cc, r2s[i]);
        }
        g_part[blk * 3 + 0] = a;
        g_part[blk * 3 + 1] = bb;
        g_part[blk * 3 + 2] = cc;
    }

    // publish clamped counts (plain stores; fully rewritten every call)
    for (int i = tid; i < NKEY; i += BIN_T)
        g_cnt[blk * NKEY + i] = min(scnt[i], SCAP);
}

// ---- store helpers ---------------------------------------------------------
__device__ __forceinline__ void store_zero(float* dst, int n, int tid, int nthr) {
    if (n <= 0) return;
    int peel = (4 - ((int)(((uintptr_t)dst >> 2) & 3))) & 3;
    if (peel > n) peel = n;
    for (int i = tid; i < peel; i += nthr) dst[i] = 0.0f;
    int n4 = (n - peel) >> 2;
    float4* d4 = (float4*)(dst + peel);
    const float4 z4 = make_float4(0.f, 0.f, 0.f, 0.f);
    for (int i = tid; i < n4; i += nthr) d4[i] = z4;
    for (int i = peel + 4 * n4 + tid; i < n; i += nthr) dst[i] = 0.0f;
}

__device__ __forceinline__ float fx2f(unsigned v) {
    return (float)(int)v * FXI;
}

__device__ __forceinline__ void store_cvt(float* dst, const unsigned* src, int n,
                                          int tid, int nthr) {
    if (n <= 0) return;
    int peel = (4 - ((int)(((uintptr_t)dst >> 2) & 3))) & 3;
    if (peel > n) peel = n;
    for (int i = tid; i < peel; i += nthr) dst[i] = fx2f(src[i]);
    int n4 = (n - peel) >> 2;
    float4* d4 = (float4*)(dst + peel);
    for (int i = tid; i < n4; i += nthr) {
        int k = peel + 4 * i;
        d4[i] = make_float4(fx2f(src[k]), fx2f(src[k + 1]),
                            fx2f(src[k + 2]), fx2f(src[k + 3]));
    }
    for (int i = peel + 4 * n4 + tid; i < n; i += nthr) dst[i] = fx2f(src[i]);
}

// shared emit: add the (q0,q1) pair at plane index e (packed when aligned)
__device__ __forceinline__ void emit_pair(unsigned* plane, int e,
                                          float w, float az) {
    unsigned q0 = __float2uint_rn(w * (1.0f - az) * FXS);
    unsigned q1 = __float2uint_rn(w * az * FXS);
    if (e & 1) {
        atomicAdd(&plane[e],     q0);
        atomicAdd(&plane[e + 1], q1);
    } else {
        atomicAdd((unsigned long long*)(plane + e),
                  ((unsigned long long)q1 << 32) | (unsigned long long)q0);
    }
}

// ---- launch 2: accumulate one (x-plane, y-group) window, write it ----------
__global__ void __launch_bounds__(256) slab_kernel(float* __restrict__ out) {
    __shared__ __align__(16) unsigned plane[PLANE_PAD];  // fixed-point 2^-25
    __shared__ int soff[2][NSUB + 1];
    __shared__ int scnt2[2][NSUB];
    __shared__ int smin[3];
    __shared__ int rs[16 * 3];

    int tid = threadIdx.x;

    // center-out tile ordering: heavy (center-x) tiles first, empty edges last
    int bid  = blockIdx.x;
    int cb   = bid & 31;
    int t    = bid >> 5;               // tile rank 0..261
    int g    = t & 1;
    int r    = t >> 1;                 // 0..130, ascending distance from center
    int half = (r + 1) >> 1;
    int ixg  = 65 + ((r & 1) ? half : -half);   // 65,66,64,67,63,...,130,0

    // -- PDL prologue: zero plane (touches nothing bin writes) ---------------
    {
        uint4* p4 = (uint4*)plane;
        const uint4 z4 = make_uint4(0u, 0u, 0u, 0u);
        for (int i = tid; i < PLANE_PAD / 4; i += blockDim.x) p4[i] = z4;
    }

    // wait for bin_kernel completion before touching g_part/g_cnt/g_pay
    cudaGridDependencySynchronize();

    // -- redundant min finalize: reduce the 256 partials ----------------------
    {
        int a = 0x7fffffff, b = 0x7fffffff, c = 0x7fffffff;
        for (int i = tid; i < NBINBLK; i += blockDim.x) {
            a = min(a, g_part[3 * i + 0]);
            b = min(b, g_part[3 * i + 1]);
            c = min(c, g_part[3 * i + 2]);
        }
        #pragma unroll
        for (int off = 16; off > 0; off >>= 1) {
            a = min(a, __shfl_xor_sync(0xffffffffu, a, off));
            b = min(b, __shfl_xor_sync(0xffffffffu, b, off));
            c = min(c, __shfl_xor_sync(0xffffffffu, c, off));
        }
        int w = tid >> 5, l = tid & 31;
        if (l == 0) { rs[w] = a; rs[16 + w] = b; rs[32 + w] = c; }
    }
    __syncthreads();

    if (tid == 0) {
        int a = rs[0], b = rs[16], c = rs[32];
        #pragma unroll
        for (int i = 1; i < 8; i++) {
            a = min(a, rs[i]); b = min(b, rs[16 + i]); c = min(c, rs[32 + i]);
        }
        smin[0] = a; smin[1] = b; smin[2] = c;
    }
    __syncthreads();
    int m0 = smin[0], m1 = smin[1], m2 = smin[2];

    // -- both x-keys' sub-counts in parallel, tiny scans ----------------------
    {
        int s = tid >> 3, u = tid & 7;
        if (tid < 2 * NSUB) {
            int xkey = ixg - s + m0 + 63;
            int cnt = 0;
            if (xkey >= 0 && xkey < 128)
                cnt = g_cnt[(cb * NSUB + u) * NKEY + xkey * 2 + g];
            scnt2[s][u] = cnt;
        }
    }
    __syncthreads();
    if (tid < 2) {
        int acc = 0;
        soff[tid][0] = 0;
        #pragma unroll
        for (int u = 0; u < NSUB; u++) {
            acc += scnt2[tid][u];
            soff[tid][u + 1] = acc;
        }
    }
    __syncthreads();

    int t0 = soff[0][NSUB];
    int t1 = soff[1][NSUB];
    int zoff = -63 - m2;

    // register-resident segment bases (sub stride = SEGSTRIDE uint2)
    int xk0 = ixg + m0 + 63;           // s = 0
    int xk1 = xk0 - 1;                 // s = 1
    const uint2* base0 = g_pay + (size_t)cb * NSUB * SEGSTRIDE
                       + (size_t)max(xk0, 0) * 2 * SCAP + (size_t)g * SCAP;
    const uint2* base1 = g_pay + (size_t)cb * NSUB * SEGSTRIDE
                       + (size_t)max(xk1, 0) * 2 * SCAP + (size_t)g * SCAP;

    // -- merged loop over both x-bins; g specialized (block-uniform) ---------
    if (g == 0) {
        for (int j = tid; j < t0 + t1; j += blockDim.x) {
            int s  = (j >= t0);
            int jj = j - (s ? t0 : 0);
            int sub = 0;
            #pragma unroll
            for (int u = 1; u < NSUB; u++) sub += (jj >= soff[s][u]);
            int local = jj - soff[s][sub];
            const uint2* bp = s ? base1 : base0;
            uint2 p = bp[(size_t)sub * SEGSTRIDE + local];

            float ax = (float)(p.x & 0xffffu) * Q16I;
            float ay = (float)(p.x >> 16)     * Q16I;
            float az = (float)(p.y & 0xffffu) * Q16I;
            unsigned pk = p.y >> 16;
            int f  = (int)(pk & 0x7fu) - 64;             // absolute fy, <= 0
            int zi = (int)((pk >> 7) & 0x7fu) + zoff;
            float wx = s ? ax : 1.0f - ax;

            int e = (f + 64) * GRID_L + zi;              // row abs f (in window)
            emit_pair(plane, e, wx * (1.0f - ay), az);
            if (f < 0)                                    // row abs f+1 <= 0
                emit_pair(plane, e + GRID_L, wx * ay, az);
        }
    } else {
        for (int j = tid; j < t0 + t1; j += blockDim.x) {
            int s  = (j >= t0);
            int jj = j - (s ? t0 : 0);
            int sub = 0;
            #pragma unroll
            for (int u = 1; u < NSUB; u++) sub += (jj >= soff[s][u]);
            int local = jj - soff[s][sub];
            const uint2* bp = s ? base1 : base0;
            uint2 p = bp[(size_t)sub * SEGSTRIDE + local];

            float ax = (float)(p.x & 0xffffu) * Q16I;
            float ay = (float)(p.x >> 16)     * Q16I;
            float az = (float)(p.y & 0xffffu) * Q16I;
            unsigned pk = p.y >> 16;
            int f  = (int)(pk & 0x7fu) - 64;             // absolute fy, >= 0
            int zi = (int)((pk >> 7) & 0x7fu) + zoff;
            float wx = s ? ax : 1.0f - ax;

            int e = f * GRID_L + zi;                     // row abs f+1 (idx f)
            emit_pair(plane, e, wx * ay, az);
            if (f >= 1)                                   // row abs f (idx f-1)
                emit_pair(plane, e - GRID_L, wx * (1.0f - ay), az);
        }
    }
    __syncthreads();

    // -- store: 3 contiguous segments (zeros / converted window / zeros) -----
    // grid row gr <-> absolute row gr + m1 - 1.
    int R0c   = min(max(2 - m1, 0), GRID_L);   // first grid row of group1
    int gr_lo = g ? R0c : 0;
    int gr_hi = g ? GRID_L : R0c;
    int Wlo   = g ? 1 : -64;                   // window absolute bounds (incl)
    int Whi   = g ? 64 : 0;
    int wg_lo = max(gr_lo, Wlo - m1 + 1);
    int wg_hi = min(gr_hi, Whi - m1 + 2);      // exclusive
    if (wg_hi < wg_lo) { wg_lo = gr_lo; wg_hi = gr_lo; }

    float* base = out + (size_t)cb * GRID_V + (size_t)ixg * GRID_P;
    store_zero(base + (size_t)gr_lo * GRID_L,
               (wg_lo - gr_lo) * GRID_L, tid, blockDim.x);
    int poff = (wg_lo + m1 - 1 - Wlo) * GRID_L;
    store_cvt(base + (size_t)wg_lo * GRID_L, plane + poff,
              (wg_hi - wg_lo) * GRID_L, tid, blockDim.x);
    store_zero(base + (size_t)wg_hi * GRID_L,
               (gr_hi - wg_hi) * GRID_L, tid, blockDim.x);
}

extern "C" void kernel_launch(void* const* d_in, const int* in_sizes, int n_in,
                              void* d_out, int out_size) {
    const float* pred = (const float*)d_in[0];
    const float* gt   = (const float*)d_in[1];
    float* out        = (float*)d_out;

    bin_kernel<<<NBINBLK, BIN_T>>>(pred, gt);

    // slab with programmatic dependent launch: prologue (plane zero) overlaps
    // the bin kernel's tail; cudaGridDependencySynchronize() gates the rest.
    cudaLaunchConfig_t cfg = {};
    cfg.gridDim  = dim3(NCB * GRID_L * 2, 1, 1);
    cfg.blockDim = dim3(256, 1, 1);
    cudaLaunchAttribute attrs[1];
    attrs[0].id = cudaLaunchAttributeProgrammaticStreamSerialization;
    attrs[0].val.programmaticStreamSerializationAllowed = 1;
    cfg.attrs = attrs;
    cfg.numAttrs = 1;
    cudaLaunchKernelEx(&cfg, slab_kernel, out);
}

// round 17
// speedup vs baseline: 1.0202x; 1.0202x over previous
#include <cuda_runtime.h>
#include <cstdint>

// GriddingDistance: trilinear scatter of two point clouds into voxel grids.
// SCALE=128, L=131, V=L^3, B=16, N=32768.
// Output: [pred_grid (16*V) | gt_grid (16*V)] floats.
//
// 2 launches (slab uses programmatic dependent launch to overlap its smem
// zero-fill prologue with the bin kernel's tail):
//  1) bin_kernel : one pass over all points, float4-vectorized reads,
//     1024-thread CTAs (latency-bound phase -> max resident warps).
//     Per-CTA partial mins + binning into per-CTA private segments keyed by
//     (x-slab, y-group). Payload packed to 8 bytes.
//  2) slab_kernel: one CTA per (cloud,batch,x-plane,y-group). Zeros its
//     plane BEFORE cudaGridDependencySynchronize(), then accumulates in
//     fixed-point smem (packed 64-bit atomics when aligned) and stores
//     3 contiguous segments (zeros / window / zeros).

#define SCALE_F   64.0f
#define GRID_L    131
#define GRID_P    (GRID_L * GRID_L)
#define GRID_V    (GRID_L * GRID_L * GRID_L)
#define BATCH     16
#define NPTS      32768
#define NCB       32                  // 2 clouds * 16 batches
#define NSUB      8                   // bin CTAs per (cloud,batch)
#define NBINBLK   (NCB * NSUB)        // 256
#define PTS_BLK   (NPTS / NSUB)       // 4096
#define NKEY      256                 // 128 x-slabs * 2 y-groups
#define SCAP      48                  // slots per (CTA,key); mean ~16
#define PLANE_PAD 8516                // 65*131=8515 rounded up to /4
#define BIN_T     1024

#define FXS       33554432.0f        // 2^25 fixed-point scale
#define FXI       (1.0f / 33554432.0f)
#define Q16       65536.0f
#define Q16I      (1.0f / 65536.0f)

__device__ int   g_part[NBINBLK * 3];                  // per-CTA partial mins
__device__ int   g_cnt[NBINBLK * NKEY];                // per-CTA per-key counts
__device__ uint2 g_pay[(size_t)NBINBLK * NKEY * SCAP]; // packed payload

// payload: p.x = axq | (ayq<<16); p.y = azq | (pk<<16)
//          pk  = (fy+64) | ((fz+64)<<7)   (7 bits each)

// ---- launch 1: partial mins + private binning (float4 reads) ---------------
__global__ void __launch_bounds__(BIN_T) bin_kernel(const float* __restrict__ pred,
                                                    const float* __restrict__ gt) {
    __shared__ int scnt[NKEY];
    __shared__ int r0s[32], r1s[32], r2s[32];

    int tid = threadIdx.x;
    int blk = blockIdx.x;
    int cb  = blk / NSUB;
    int sub = blk % NSUB;
    int c   = cb >> 4;
    int b   = cb & 15;
    const float* cloud = (c ? gt : pred) + 3 * ((size_t)b * NPTS + sub * PTS_BLK);
    const float4* c4 = reinterpret_cast<const float4*>(cloud);  // 16B-aligned

    for (int i = tid; i < NKEY; i += BIN_T) scnt[i] = 0;
    __syncthreads();

    uint2* seg = g_pay + (size_t)blk * NKEY * SCAP;

    int mn0 = 0x7fffffff, mn1 = 0x7fffffff, mn2 = 0x7fffffff;

    const int nq = PTS_BLK / 4;                    // 1024 quads of 4 points
    for (int qi = tid; qi < nq; qi += BIN_T) {
        float4 A = c4[3 * qi + 0];
        float4 B = c4[3 * qi + 1];
        float4 C = c4[3 * qi + 2];
        float px[4], py[4], pz[4];
        px[0] = A.x; py[0] = A.y; pz[0] = A.z;
        px[1] = A.w; py[1] = B.x; pz[1] = B.y;
        px[2] = B.z; py[2] = B.w; pz[2] = C.x;
        px[3] = C.y; py[3] = C.z; pz[3] = C.w;

        #pragma unroll
        for (int k = 0; k < 4; k++) {
            float x = px[k] * SCALE_F;
            float y = py[k] * SCALE_F;
            float z = pz[k] * SCALE_F;
            float fx = floorf(x), fy = floorf(y), fz = floorf(z);
            // mins include padding points (reference: mins before masking)
            mn0 = min(mn0, (int)fx);
            mn1 = min(mn1, (int)fy);
            mn2 = min(mn2, (int)fz);
            if (x + y + z == 0.0f) continue;       // padding point: not binned
            int xkey = (int)fx + 64;               // 0..127
            if ((unsigned)xkey >= 128u) continue;  // safety (cannot happen)
            int f = (int)fy;                       // absolute fy, in [-64,63]

            unsigned axq = min(__float2uint_rn((x - fx) * Q16), 65535u);
            unsigned ayq = min(__float2uint_rn((y - fy) * Q16), 65535u);
            unsigned azq = min(__float2uint_rn((z - fz) * Q16), 65535u);
            unsigned pk  = (unsigned)(f + 64) | ((unsigned)((int)fz + 64) << 7);
            uint2 pay = make_uint2(axq | (ayq << 16), azq | (pk << 16));

            if (f <= 0) {                          // group0 (abs rows -64..0)
                int key = xkey * 2;
                int pos = atomicAdd(&scnt[key], 1);
                if (pos < SCAP) seg[key * SCAP + pos] = pay;
            }
            if (f >= 0) {                          // group1 (abs rows 1..64)
                int key = xkey * 2 + 1;
                int pos = atomicAdd(&scnt[key], 1);
                if (pos < SCAP) seg[key * SCAP + pos] = pay;
            }
        }
    }

    // reduce partial mins
    #pragma unroll
    for (int off = 16; off > 0; off >>= 1) {
        mn0 = min(mn0, __shfl_xor_sync(0xffffffffu, mn0, off));
        mn1 = min(mn1, __shfl_xor_sync(0xffffffffu, mn1, off));
        mn2 = min(mn2, __shfl_xor_sync(0xffffffffu, mn2, off));
    }
    int w = tid >> 5, l = tid & 31;
    if (l == 0) { r0s[w] = mn0; r1s[w] = mn1; r2s[w] = mn2; }
    __syncthreads();
    if (tid == 0) {
        int a = r0s[0], bb = r1s[0], cc = r2s[0];
        #pragma unroll
        for (int i = 1; i < 32; i++) {
            a = min(a, r0s[i]); bb = min(bb, r1s[i]); cc = min(cc, r2s[i]);
        }
        g_part[blk * 3 + 0] = a;
        g_part[blk * 3 + 1] = bb;
        g_part[blk * 3 + 2] = cc;
    }

    // publish clamped counts (plain stores; fully rewritten every call)
    for (int i = tid; i < NKEY; i += BIN_T)
        g_cnt[blk * NKEY + i] = min(scnt[i], SCAP);
}

// ---- store helpers ---------------------------------------------------------
__device__ __forceinline__ void store_zero(float* dst, int n, int tid, int nthr) {
    if (n <= 0) return;
    int peel = (4 - ((int)(((uintptr_t)dst >> 2) & 3))) & 3;
    if (peel > n) peel = n;
    for (int i = tid; i < peel; i += nthr) dst[i] = 0.0f;
    int n4 = (n - peel) >> 2;
    float4* d4 = (float4*)(dst + peel);
    const float4 z4 = make_float4(0.f, 0.f, 0.f, 0.f);
    for (int i = tid; i < n4; i += nthr) d4[i] = z4;
    for (int i = peel + 4 * n4 + tid; i < n; i += nthr) dst[i] = 0.0f;
}

__device__ __forceinline__ float fx2f(unsigned v) {
    return (float)(int)v * FXI;
}

__device__ __forceinline__ void store_cvt(float* dst, const unsigned* src, int n,
                                          int tid, int nthr) {
    if (n <= 0) return;
    int peel = (4 - ((int)(((uintptr_t)dst >> 2) & 3))) & 3;
    if (peel > n) peel = n;
    for (int i = tid; i < peel; i += nthr) dst[i] = fx2f(src[i]);
    int n4 = (n - peel) >> 2;
    float4* d4 = (float4*)(dst + peel);
    for (int i = tid; i < n4; i += nthr) {
        int k = peel + 4 * i;
        d4[i] = make_float4(fx2f(src[k]), fx2f(src[k + 1]),
                            fx2f(src[k + 2]), fx2f(src[k + 3]));
    }
    for (int i = peel + 4 * n4 + tid; i < n; i += nthr) dst[i] = fx2f(src[i]);
}

// shared emit: add the (q0,q1) pair at plane index e (packed when aligned)
__device__ __forceinline__ void emit_pair(unsigned* plane, int e,
                                          float w, float az) {
    unsigned q0 = __float2uint_rn(w * (1.0f - az) * FXS);
    unsigned q1 = __float2uint_rn(w * az * FXS);
    if (e & 1) {
        atomicAdd(&plane[e],     q0);
        atomicAdd(&plane[e + 1], q1);
    } else {
        atomicAdd((unsigned long long*)(plane + e),
                  ((unsigned long long)q1 << 32) | (unsigned long long)q0);
    }
}

// ---- launch 2: accumulate one (x-plane, y-group) window, write it ----------
__global__ void __launch_bounds__(256) slab_kernel(float* __restrict__ out) {
    __shared__ __align__(16) unsigned plane[PLANE_PAD];  // fixed-point 2^-25
    __shared__ int soff[2][NSUB + 1];
    __shared__ int scnt2[2][NSUB];
    __shared__ int smin[3];
    __shared__ int rs[16 * 3];

    int tid = threadIdx.x;
    int bid = blockIdx.x;
    int cb  = bid / (GRID_L * 2);
    int rem = bid - cb * (GRID_L * 2);
    int ixg = rem >> 1;
    int g   = rem & 1;

    // -- PDL prologue: zero plane (touches nothing bin writes) ---------------
    {
        uint4* p4 = (uint4*)plane;
        const uint4 z4 = make_uint4(0u, 0u, 0u, 0u);
        for (int i = tid; i < PLANE_PAD / 4; i += blockDim.x) p4[i] = z4;
    }

    // wait for bin_kernel completion before touching g_part/g_cnt/g_pay
    cudaGridDependencySynchronize();

    // -- redundant min finalize: reduce the 256 partials ----------------------
    {
        int a = 0x7fffffff, b = 0x7fffffff, c = 0x7fffffff;
        for (int i = tid; i < NBINBLK; i += blockDim.x) {
            a = min(a, g_part[3 * i + 0]);
            b = min(b, g_part[3 * i + 1]);
            c = min(c, g_part[3 * i + 2]);
        }
        #pragma unroll
        for (int off = 16; off > 0; off >>= 1) {
            a = min(a, __shfl_xor_sync(0xffffffffu, a, off));
            b = min(b, __shfl_xor_sync(0xffffffffu, b, off));
            c = min(c, __shfl_xor_sync(0xffffffffu, c, off));
        }
        int w = tid >> 5, l = tid & 31;
        if (l == 0) { rs[w] = a; rs[16 + w] = b; rs[32 + w] = c; }
    }
    __syncthreads();

    if (tid == 0) {
        int a = rs[0], b = rs[16], c = rs[32];
        #pragma unroll
        for (int i = 1; i < 8; i++) {
            a = min(a, rs[i]); b = min(b, rs[16 + i]); c = min(c, rs[32 + i]);
        }
        smin[0] = a; smin[1] = b; smin[2] = c;
    }
    __syncthreads();
    int m0 = smin[0], m1 = smin[1], m2 = smin[2];

    // -- both x-keys' sub-counts in parallel, tiny scans ----------------------
    {
        int s = tid >> 3, u = tid & 7;
        if (tid < 2 * NSUB) {
            int xkey = ixg - s + m0 + 63;
            int cnt = 0;
            if (xkey >= 0 && xkey < 128)
                cnt = g_cnt[(cb * NSUB + u) * NKEY + xkey * 2 + g];
            scnt2[s][u] = cnt;
        }
    }
    __syncthreads();
    if (tid < 2) {
        int acc = 0;
        soff[tid][0] = 0;
        #pragma unroll
        for (int u = 0; u < NSUB; u++) {
            acc += scnt2[tid][u];
            soff[tid][u + 1] = acc;
        }
    }
    __syncthreads();

    int t0 = soff[0][NSUB];
    int t1 = soff[1][NSUB];
    int zoff = -63 - m2;

    // -- merged loop over both x-bins; g specialized (block-uniform) ---------
    if (g == 0) {
        for (int j = tid; j < t0 + t1; j += blockDim.x) {
            int s  = (j >= t0);
            int jj = j - (s ? t0 : 0);
            int xkey = ixg - s + m0 + 63;
            int key  = xkey * 2;

            int sub = 0;
            #pragma unroll
            for (int u = 1; u < NSUB; u++) sub += (jj >= soff[s][u]);
            int local = jj - soff[s][sub];
            uint2 p = g_pay[((size_t)(cb * NSUB + sub) * NKEY + key) * SCAP + local];

            float ax = (float)(p.x & 0xffffu) * Q16I;
            float ay = (float)(p.x >> 16)     * Q16I;
            float az = (float)(p.y & 0xffffu) * Q16I;
            unsigned pk = p.y >> 16;
            int f  = (int)(pk & 0x7fu) - 64;             // absolute fy, <= 0
            int zi = (int)((pk >> 7) & 0x7fu) + zoff;
            float wx = s ? ax : 1.0f - ax;

            int e = (f + 64) * GRID_L + zi;              // row abs f (in window)
            emit_pair(plane, e, wx * (1.0f - ay), az);
            if (f < 0)                                    // row abs f+1 <= 0
                emit_pair(plane, e + GRID_L, wx * ay, az);
        }
    } else {
        for (int j = tid; j < t0 + t1; j += blockDim.x) {
            int s  = (j >= t0);
            int jj = j - (s ? t0 : 0);
            int xkey = ixg - s + m0 + 63;
            int key  = xkey * 2 + 1;

            int sub = 0;
            #pragma unroll
            for (int u = 1; u < NSUB; u++) sub += (jj >= soff[s][u]);
            int local = jj - soff[s][sub];
            uint2 p = g_pay[((size_t)(cb * NSUB + sub) * NKEY + key) * SCAP + local];

            float ax = (float)(p.x & 0xffffu) * Q16I;
            float ay = (float)(p.x >> 16)     * Q16I;
            float az = (float)(p.y & 0xffffu) * Q16I;
            unsigned pk = p.y >> 16;
            int f  = (int)(pk & 0x7fu) - 64;             // absolute fy, >= 0
            int zi = (int)((pk >> 7) & 0x7fu) + zoff;
            float wx = s ? ax : 1.0f - ax;

            int e = f * GRID_L + zi;                     // row abs f+1 (idx f)
            emit_pair(plane, e, wx * ay, az);
            if (f >= 1)                                   // row abs f (idx f-1)
                emit_pair(plane, e - GRID_L, wx * (1.0f - ay), az);
        }
    }
    __syncthreads();

    // -- store: 3 contiguous segments (zeros / converted window / zeros) -----
    // grid row gr <-> absolute row gr + m1 - 1.
    int R0c   = min(max(2 - m1, 0), GRID_L);   // first grid row of group1
    int gr_lo = g ? R0c : 0;
    int gr_hi = g ? GRID_L : R0c;
    int Wlo   = g ? 1 : -64;                   // window absolute bounds (incl)
    int Whi   = g ? 64 : 0;
    int wg_lo = max(gr_lo, Wlo - m1 + 1);
    int wg_hi = min(gr_hi, Whi - m1 + 2);      // exclusive
    if (wg_hi < wg_lo) { wg_lo = gr_lo; wg_hi = gr_lo; }

    float* base = out + (size_t)cb * GRID_V + (size_t)ixg * GRID_P;
    store_zero(base + (size_t)gr_lo * GRID_L,
               (wg_lo - gr_lo) * GRID_L, tid, blockDim.x);
    int poff = (wg_lo + m1 - 1 - Wlo) * GRID_L;
    store_cvt(base + (size_t)wg_lo * GRID_L, plane + poff,
              (wg_hi - wg_lo) * GRID_L, tid, blockDim.x);
    store_zero(base + (size_t)wg_hi * GRID_L,
               (gr_hi - wg_hi) * GRID_L, tid, blockDim.x);
}

extern "C" void kernel_launch(void* const* d_in, const int* in_sizes, int n_in,
                              void* d_out, int out_size) {
    const float* pred = (const float*)d_in[0];
    const float* gt   = (const float*)d_in[1];
    float* out        = (float*)d_out;

    bin_kernel<<<NBINBLK, BIN_T>>>(pred, gt);

    // slab with programmatic dependent launch: prologue (plane zero) overlaps
    // the bin kernel's tail; cudaGridDependencySynchronize() gates the rest.
    cudaLaunchConfig_t cfg = {};
    cfg.gridDim  = dim3(NCB * GRID_L * 2, 1, 1);
    cfg.blockDim = dim3(256, 1, 1);
    cudaLaunchAttribute attrs[1];
    attrs[0].id = cudaLaunchAttributeProgrammaticStreamSerialization;
    attrs[0].val.programmaticStreamSerializationAllowed = 1;
    cfg.attrs = attrs;
    cfg.numAttrs = 1;
    cudaLaunchKernelEx(&cfg, slab_kernel, out);
}